// round 1
// baseline (speedup 1.0000x reference)
#include <cuda_runtime.h>

#define W 512
#define H 512
#define BATCH 2
#define HW (H*W)
#define NCV (BATCH*(H-1)*W)
#define NCH (BATCH*H*(W-1))
#define L_STEP 0.24f
#define KK 0.0009f   /* 0.03*0.03 */

#define TW 128
#define TH 64
#define HALO 8
#define TSX (TW - 2*HALO)   /* 112 interior width  */
#define TSY (TH - 2*HALO)   /* 48  interior height */
#define NBX 5               /* ceil(512/112) */
#define NBY 11              /* ceil(512/48)  */
#define NTI 32              /* thread-columns (x) */
#define NTJ 16              /* thread-rows (y)    */
#define NTHREADS (NTI*NTJ)
#define LPAD (TH + 4)       /* 68 floats: pad to break bank conflicts */

/* ping-pong state + premultiplied conductances (scratch via __device__ globals) */
__device__ float g_I0[BATCH*HW];
__device__ float g_I1[BATCH*HW];
__device__ float g_cvL[NCV];
__device__ float g_chL[NCH];

/* ---- conductance kernels: write raw g to d_out region, L*g to scratch ---- */
__global__ void k_coeff_v(const float* __restrict__ guide, float* __restrict__ out_cv) {
    int idx = blockIdx.x*blockDim.x + threadIdx.x;
    if (idx >= NCV) return;
    int x = idx % W;
    int y = (idx / W) % (H-1);
    int b = idx / (W*(H-1));
    const float* gb = guide + (size_t)b*3*HW + (size_t)y*W + x;
    float s = 0.f;
    #pragma unroll
    for (int c = 0; c < 3; c++) s += fabsf(gb[(size_t)c*HW + W] - gb[(size_t)c*HW]);
    float m = s * (1.0f/3.0f);
    float g = 1.0f / (1.0f + (m*m)/KK);
    out_cv[idx] = g;
    g_cvL[idx]  = L_STEP * g;
}

__global__ void k_coeff_h(const float* __restrict__ guide, float* __restrict__ out_ch) {
    int idx = blockIdx.x*blockDim.x + threadIdx.x;
    if (idx >= NCH) return;
    int x = idx % (W-1);
    int y = (idx / (W-1)) % H;
    int b = idx / ((W-1)*H);
    const float* gb = guide + (size_t)b*3*HW + (size_t)y*W + x;
    float s = 0.f;
    #pragma unroll
    for (int c = 0; c < 3; c++) s += fabsf(gb[(size_t)c*HW + 1] - gb[(size_t)c*HW]);
    float m = s * (1.0f/3.0f);
    float g = 1.0f / (1.0f + (m*m)/KK);
    out_ch[idx] = g;
    g_chL[idx]  = L_STEP * g;
}

__global__ void k_copy_in(const float* __restrict__ initial) {
    int idx = blockIdx.x*blockDim.x + threadIdx.x;
    if (idx < BATCH*HW) g_I0[idx] = initial[idx];
}

__global__ void k_output(float* __restrict__ out_y) {
    int idx = blockIdx.x*blockDim.x + threadIdx.x;
    if (idx < BATCH*HW) out_y[idx] = g_I1[idx];
}

/* ---- temporal-blocked diffusion: T<=8 steps per launch ----
 * Each thread holds a 4x4 register block of I plus the 5x4 cvL / 4x5 chL
 * coefficients it needs. Per step only the block perimeter is exchanged
 * through shared memory (all float4). Zero coefficients outside the valid
 * coefficient range make image boundaries exact; tile-halo garbage advances
 * one cell per step so the [HALO, size-HALO) interior stays exact. */
__global__ void __launch_bounds__(NTHREADS, 1)
k_diffuse(int parity, int nsteps) {
    const float* __restrict__ src = parity ? g_I1 : g_I0;
    float*       __restrict__ dst = parity ? g_I0 : g_I1;

    __shared__ float sTop[NTJ][TW];
    __shared__ float sBot[NTJ][TW];
    __shared__ float sLeft[NTI][LPAD];
    __shared__ float sRight[NTI][LPAD];

    const int tid = threadIdx.x;
    const int ti  = tid & 31;
    const int tj  = tid >> 5;
    const int bx = blockIdx.x, by = blockIdx.y, b = blockIdx.z;

    const int ox  = bx*TSX - HALO;
    const int oy  = by*TSY - HALO;
    const int lx0 = ti*4, ly0 = tj*4;
    const int gx0 = ox + lx0;
    const int gy0 = oy + ly0;

    const float* __restrict__ srcb = src + (size_t)b*HW;
    float*       __restrict__ dstb = dst + (size_t)b*HW;
    const float* __restrict__ cvb  = g_cvL + (size_t)b*(H-1)*W;
    const float* __restrict__ chb  = g_chL + (size_t)b*H*(W-1);

    /* x-blocks are 4-aligned and the 0/512 edges are multiples of 4, so a
     * block is either fully inside [0,W) in x or fully outside. */
    const bool xok = (gx0 >= 0) && (gx0 + 4 <= W);

    float I[4][4];
    #pragma unroll
    for (int j = 0; j < 4; j++) {
        int gy = gy0 + j;
        if (xok && gy >= 0 && gy < H) {
            float4 v = *(const float4*)(srcb + (size_t)gy*W + gx0);
            I[j][0]=v.x; I[j][1]=v.y; I[j][2]=v.z; I[j][3]=v.w;
        } else {
            I[j][0]=0.f; I[j][1]=0.f; I[j][2]=0.f; I[j][3]=0.f;
        }
    }

    float CV[5][4];   /* rows gy0-1 .. gy0+3 of L*cv */
    #pragma unroll
    for (int jj = 0; jj < 5; jj++) {
        int r = gy0 - 1 + jj;
        if (xok && r >= 0 && r < H-1) {
            float4 v = *(const float4*)(cvb + (size_t)r*W + gx0);
            CV[jj][0]=v.x; CV[jj][1]=v.y; CV[jj][2]=v.z; CV[jj][3]=v.w;
        } else {
            CV[jj][0]=0.f; CV[jj][1]=0.f; CV[jj][2]=0.f; CV[jj][3]=0.f;
        }
    }

    float CH[4][5];   /* cols gx0-1 .. gx0+3 of L*ch */
    #pragma unroll
    for (int j = 0; j < 4; j++) {
        int gy = gy0 + j;
        #pragma unroll
        for (int ii = 0; ii < 5; ii++) {
            int c = gx0 - 1 + ii;
            CH[j][ii] = (gy >= 0 && gy < H && c >= 0 && c < W-1)
                      ? chb[(size_t)gy*(W-1) + c] : 0.f;
        }
    }

    for (int s = 0; s < nsteps; s++) {
        /* publish perimeter */
        *(float4*)&sTop [tj][lx0] = make_float4(I[0][0],I[0][1],I[0][2],I[0][3]);
        *(float4*)&sBot [tj][lx0] = make_float4(I[3][0],I[3][1],I[3][2],I[3][3]);
        *(float4*)&sLeft[ti][ly0] = make_float4(I[0][0],I[1][0],I[2][0],I[3][0]);
        *(float4*)&sRight[ti][ly0]= make_float4(I[0][3],I[1][3],I[2][3],I[3][3]);
        __syncthreads();
        float4 upv = (tj > 0)     ? *(float4*)&sBot [tj-1][lx0] : make_float4(0,0,0,0);
        float4 dnv = (tj < NTJ-1) ? *(float4*)&sTop [tj+1][lx0] : make_float4(0,0,0,0);
        float4 lfv = (ti > 0)     ? *(float4*)&sRight[ti-1][ly0] : make_float4(0,0,0,0);
        float4 rtv = (ti < NTI-1) ? *(float4*)&sLeft [ti+1][ly0] : make_float4(0,0,0,0);
        __syncthreads();
        float up[4] = {upv.x, upv.y, upv.z, upv.w};
        float dn[4] = {dnv.x, dnv.y, dnv.z, dnv.w};
        float lf[4] = {lfv.x, lfv.y, lfv.z, lfv.w};
        float rt[4] = {rtv.x, rtv.y, rtv.z, rtv.w};

        float N_[4][4];
        /* vertical: N = (I - tv_up) + tv_down  (matches ref add order) */
        #pragma unroll
        for (int i = 0; i < 4; i++) {
            float f0 = CV[0][i] * (I[0][i] - up[i]);
            float f1 = CV[1][i] * (I[1][i] - I[0][i]);
            float f2 = CV[2][i] * (I[2][i] - I[1][i]);
            float f3 = CV[3][i] * (I[3][i] - I[2][i]);
            float f4 = CV[4][i] * (dn[i]   - I[3][i]);
            N_[0][i] = (I[0][i] - f0) + f1;
            N_[1][i] = (I[1][i] - f1) + f2;
            N_[2][i] = (I[2][i] - f2) + f3;
            N_[3][i] = (I[3][i] - f3) + f4;
        }
        /* horizontal (dh from the pre-update I): I = (N - th_l) + th_r */
        #pragma unroll
        for (int j = 0; j < 4; j++) {
            float g0 = CH[j][0] * (I[j][0] - lf[j]);
            float g1 = CH[j][1] * (I[j][1] - I[j][0]);
            float g2 = CH[j][2] * (I[j][2] - I[j][1]);
            float g3 = CH[j][3] * (I[j][3] - I[j][2]);
            float g4 = CH[j][4] * (rt[j]   - I[j][3]);
            I[j][0] = (N_[j][0] - g0) + g1;
            I[j][1] = (N_[j][1] - g1) + g2;
            I[j][2] = (N_[j][2] - g2) + g3;
            I[j][3] = (N_[j][3] - g3) + g4;
        }
    }

    /* write back interior (block-granular in x/ly; per-row image clip in y) */
    if (xok && lx0 >= HALO && lx0 < TW - HALO) {
        #pragma unroll
        for (int j = 0; j < 4; j++) {
            int ly = ly0 + j;
            int gy = gy0 + j;
            if (ly >= HALO && ly < TH - HALO && gy < H) {
                *(float4*)(dstb + (size_t)gy*W + gx0) =
                    make_float4(I[j][0], I[j][1], I[j][2], I[j][3]);
            }
        }
    }
}

extern "C" void kernel_launch(void* const* d_in, const int* in_sizes, int n_in,
                              void* d_out, int out_size) {
    const float* a0 = (const float*)d_in[0];
    const float* a1 = (const float*)d_in[1];
    const float* guide = a0;
    const float* initial = a1;
    if (n_in >= 2 && in_sizes[0] < in_sizes[1]) { guide = a1; initial = a0; }

    float* out    = (float*)d_out;
    float* out_y  = out;                       /* [BATCH*HW]   */
    float* out_cv = out + BATCH*HW;            /* [NCV]        */
    float* out_ch = out_cv + NCV;              /* [NCH]        */

    k_coeff_v<<<(NCV + 255)/256, 256>>>(guide, out_cv);
    k_coeff_h<<<(NCH + 255)/256, 256>>>(guide, out_ch);
    k_copy_in<<<(BATCH*HW + 255)/256, 256>>>(initial);

    dim3 grid(NBX, NBY, BATCH);
    int done = 0, p = 0;
    while (done < 500) {
        int s = (500 - done) < HALO ? (500 - done) : HALO;
        k_diffuse<<<grid, NTHREADS>>>(p & 1, s);
        done += s;
        p++;
    }
    /* 63 phases, last writes g_I1 */
    k_output<<<(BATCH*HW + 255)/256, 256>>>(out_y);
}

// round 3
// speedup vs baseline: 1.1744x; 1.1744x over previous
#include <cuda_runtime.h>

#define W 512
#define H 512
#define BATCH 2
#define HW (H*W)
#define NCV (BATCH*(H-1)*W)
#define NCH (BATCH*H*(W-1))
#define L_STEP 0.24f
#define KK 0.0009f   /* 0.03*0.03 */

#define TW 128
#define TH 64
#define HALO 8
#define TSX (TW - 2*HALO)   /* 112 interior width  */
#define TSY (TH - 2*HALO)   /* 48  interior height */
#define NBX 5               /* ceil(512/112) */
#define NBY 11              /* ceil(512/48)  */
#define NTI 32              /* thread-columns (x) == lane id */
#define NTJ 16              /* thread-rows (y)    == warp id */
#define NTHREADS (NTI*NTJ)
#define NCTAS (NBX*NBY*BATCH)   /* 110 <= 148 SMs: co-resident, grid barrier safe */
#define NPH 63                  /* 62*8 + 4 = 500 steps */

/* scratch state (ping-pong) + premultiplied conductances + barrier flags */
__device__ float g_I0[BATCH*HW];
__device__ float g_I1[BATCH*HW];
__device__ float g_cvL[NCV];
__device__ float g_chL[NCH];
__device__ unsigned g_flags[NCTAS];

/* ---- conductance kernels: raw g to d_out region, L*g to scratch ---- */
__global__ void k_coeff_v(const float* __restrict__ guide, float* __restrict__ out_cv) {
    int idx = blockIdx.x*blockDim.x + threadIdx.x;
    if (idx >= NCV) return;
    int x = idx % W;
    int y = (idx / W) % (H-1);
    int b = idx / (W*(H-1));
    const float* gb = guide + (size_t)b*3*HW + (size_t)y*W + x;
    float s = 0.f;
    #pragma unroll
    for (int c = 0; c < 3; c++) s += fabsf(gb[(size_t)c*HW + W] - gb[(size_t)c*HW]);
    float m = s * (1.0f/3.0f);
    float g = 1.0f / (1.0f + (m*m)/KK);
    out_cv[idx] = g;
    g_cvL[idx]  = L_STEP * g;
}

__global__ void k_coeff_h(const float* __restrict__ guide, float* __restrict__ out_ch) {
    int idx = blockIdx.x*blockDim.x + threadIdx.x;
    if (idx >= NCH) return;
    int x = idx % (W-1);
    int y = (idx / (W-1)) % H;
    int b = idx / ((W-1)*H);
    const float* gb = guide + (size_t)b*3*HW + (size_t)y*W + x;
    float s = 0.f;
    #pragma unroll
    for (int c = 0; c < 3; c++) s += fabsf(gb[(size_t)c*HW + 1] - gb[(size_t)c*HW]);
    float m = s * (1.0f/3.0f);
    float g = 1.0f / (1.0f + (m*m)/KK);
    out_ch[idx] = g;
    g_chL[idx]  = L_STEP * g;
}

__global__ void k_reset() {
    int idx = threadIdx.x;
    if (idx < NCTAS) g_flags[idx] = 0u;
}

__device__ __forceinline__ void flag_store_release(unsigned* p, unsigned v) {
    asm volatile("st.release.gpu.u32 [%0], %1;" :: "l"(p), "r"(v) : "memory");
}
__device__ __forceinline__ unsigned flag_load_acquire(const unsigned* p) {
    unsigned v;
    asm volatile("ld.acquire.gpu.u32 %0, [%1];" : "=r"(v) : "l"(p) : "memory");
    return v;
}

/* software grid barrier: all NCTAS CTAs are co-resident (1 CTA/SM, 110<=148).
 * Arrival: one release store per CTA; wait: NCTAS threads poll distinct flags
 * with nanosleep backoff. */
__device__ __forceinline__ void grid_barrier(int cta, unsigned target) {
    __syncthreads();                    /* all CTA threads finished their STGs */
    if (threadIdx.x == 0) {
        flag_store_release(&g_flags[cta], target);
    }
    if (threadIdx.x < NCTAS) {
        while (flag_load_acquire(&g_flags[threadIdx.x]) < target) {
            __nanosleep(32);
        }
    }
    __syncthreads();                    /* every flag observed by someone */
}

/* ---- persistent temporal-blocked diffusion ----
 * Thread-private 4x4 register block; coefficients (5x4 cvL, 4x5 chL) live in
 * registers for ALL 500 steps. Per step: top/bottom perimeter via
 * double-buffered smem (one __syncthreads), left/right via warp shuffles.
 * Every 8 steps: write interior, grid barrier, reload 4x4 from ping-pong. */
__global__ void __launch_bounds__(NTHREADS, 1)
k_persist(const float* __restrict__ initial, float* __restrict__ out_y) {
    __shared__ float sTop[2][NTJ][TW];
    __shared__ float sBot[2][NTJ][TW];

    const int tid = threadIdx.x;
    const int ti  = tid & 31;          /* lane id  = x thread-column */
    const int tj  = tid >> 5;          /* warp id  = y thread-row    */
    const int bx = blockIdx.x, by = blockIdx.y, b = blockIdx.z;
    const int cta = bx + NBX*(by + NBY*b);

    const int ox  = bx*TSX - HALO;
    const int oy  = by*TSY - HALO;
    const int lx0 = ti*4, ly0 = tj*4;
    const int gx0 = ox + lx0;
    const int gy0 = oy + ly0;
    const bool xok = (gx0 >= 0) && (gx0 + 4 <= W);

    const float* __restrict__ cvb = g_cvL + (size_t)b*(H-1)*W;
    const float* __restrict__ chb = g_chL + (size_t)b*H*(W-1);

    /* persistent coefficient registers */
    float CV[5][4];   /* rows gy0-1 .. gy0+3 of L*cv */
    #pragma unroll
    for (int jj = 0; jj < 5; jj++) {
        int r = gy0 - 1 + jj;
        if (xok && r >= 0 && r < H-1) {
            float4 v = *(const float4*)(cvb + (size_t)r*W + gx0);
            CV[jj][0]=v.x; CV[jj][1]=v.y; CV[jj][2]=v.z; CV[jj][3]=v.w;
        } else {
            CV[jj][0]=0.f; CV[jj][1]=0.f; CV[jj][2]=0.f; CV[jj][3]=0.f;
        }
    }
    float CH[4][5];   /* cols gx0-1 .. gx0+3 of L*ch */
    #pragma unroll
    for (int j = 0; j < 4; j++) {
        int gy = gy0 + j;
        #pragma unroll
        for (int ii = 0; ii < 5; ii++) {
            int c = gx0 - 1 + ii;
            CH[j][ii] = (gy >= 0 && gy < H && c >= 0 && c < W-1)
                      ? chb[(size_t)gy*(W-1) + c] : 0.f;
        }
    }

    /* initial state straight from input */
    float I[4][4];
    {
        const float* __restrict__ srcb = initial + (size_t)b*HW;
        #pragma unroll
        for (int j = 0; j < 4; j++) {
            int gy = gy0 + j;
            if (xok && gy >= 0 && gy < H) {
                float4 v = *(const float4*)(srcb + (size_t)gy*W + gx0);
                I[j][0]=v.x; I[j][1]=v.y; I[j][2]=v.z; I[j][3]=v.w;
            } else {
                I[j][0]=0.f; I[j][1]=0.f; I[j][2]=0.f; I[j][3]=0.f;
            }
        }
    }

    for (int p = 0; p < NPH; p++) {
        const int nsteps = (p == NPH-1) ? 4 : HALO;
        for (int s = 0; s < nsteps; s++) {
            const int bs = s & 1;
            /* publish top/bottom perimeter (pre-update values) */
            *(float4*)&sTop[bs][tj][lx0] = make_float4(I[0][0],I[0][1],I[0][2],I[0][3]);
            *(float4*)&sBot[bs][tj][lx0] = make_float4(I[3][0],I[3][1],I[3][2],I[3][3]);
            /* left/right neighbors via shuffles (pre-update values);
             * lane-0/31 garbage is confined to zero-coefficient halo cells */
            float lf[4], rt[4];
            #pragma unroll
            for (int j = 0; j < 4; j++) {
                lf[j] = __shfl_up_sync  (0xffffffffu, I[j][3], 1);
                rt[j] = __shfl_down_sync(0xffffffffu, I[j][0], 1);
            }
            __syncthreads();
            float4 upv = (tj > 0)     ? *(float4*)&sBot[bs][tj-1][lx0] : make_float4(0,0,0,0);
            float4 dnv = (tj < NTJ-1) ? *(float4*)&sTop[bs][tj+1][lx0] : make_float4(0,0,0,0);
            float up[4] = {upv.x, upv.y, upv.z, upv.w};
            float dn[4] = {dnv.x, dnv.y, dnv.z, dnv.w};

            float N_[4][4];
            /* vertical: N = (I - tv_up) + tv_down */
            #pragma unroll
            for (int i = 0; i < 4; i++) {
                float f0 = CV[0][i] * (I[0][i] - up[i]);
                float f1 = CV[1][i] * (I[1][i] - I[0][i]);
                float f2 = CV[2][i] * (I[2][i] - I[1][i]);
                float f3 = CV[3][i] * (I[3][i] - I[2][i]);
                float f4 = CV[4][i] * (dn[i]   - I[3][i]);
                N_[0][i] = (I[0][i] - f0) + f1;
                N_[1][i] = (I[1][i] - f1) + f2;
                N_[2][i] = (I[2][i] - f2) + f3;
                N_[3][i] = (I[3][i] - f3) + f4;
            }
            /* horizontal (dh from pre-update I): I = (N - th_l) + th_r */
            #pragma unroll
            for (int j = 0; j < 4; j++) {
                float g0 = CH[j][0] * (I[j][0] - lf[j]);
                float g1 = CH[j][1] * (I[j][1] - I[j][0]);
                float g2 = CH[j][2] * (I[j][2] - I[j][1]);
                float g3 = CH[j][3] * (I[j][3] - I[j][2]);
                float g4 = CH[j][4] * (rt[j]   - I[j][3]);
                I[j][0] = (N_[j][0] - g0) + g1;
                I[j][1] = (N_[j][1] - g1) + g2;
                I[j][2] = (N_[j][2] - g2) + g3;
                I[j][3] = (N_[j][3] - g3) + g4;
            }
        }

        /* write interior: last phase straight to output, else ping-pong */
        float* __restrict__ wb = (p == NPH-1)
            ? (out_y + (size_t)b*HW)
            : (((p & 1) ? g_I0 : g_I1) + (size_t)b*HW);
        if (xok && lx0 >= HALO && lx0 < TW - HALO) {
            #pragma unroll
            for (int j = 0; j < 4; j++) {
                int ly = ly0 + j;
                int gy = gy0 + j;
                if (ly >= HALO && ly < TH - HALO && gy < H) {
                    *(float4*)(wb + (size_t)gy*W + gx0) =
                        make_float4(I[j][0], I[j][1], I[j][2], I[j][3]);
                }
            }
        }

        if (p < NPH-1) {
            grid_barrier(cta, (unsigned)(p + 1));
            const float* __restrict__ rb = ((p & 1) ? g_I0 : g_I1) + (size_t)b*HW;
            #pragma unroll
            for (int j = 0; j < 4; j++) {
                int gy = gy0 + j;
                if (xok && gy >= 0 && gy < H) {
                    float4 v = *(const float4*)(rb + (size_t)gy*W + gx0);
                    I[j][0]=v.x; I[j][1]=v.y; I[j][2]=v.z; I[j][3]=v.w;
                } else {
                    I[j][0]=0.f; I[j][1]=0.f; I[j][2]=0.f; I[j][3]=0.f;
                }
            }
        }
    }
}

extern "C" void kernel_launch(void* const* d_in, const int* in_sizes, int n_in,
                              void* d_out, int out_size) {
    const float* a0 = (const float*)d_in[0];
    const float* a1 = (const float*)d_in[1];
    const float* guide = a0;
    const float* initial = a1;
    if (n_in >= 2 && in_sizes[0] < in_sizes[1]) { guide = a1; initial = a0; }

    float* out    = (float*)d_out;
    float* out_y  = out;                       /* [BATCH*HW]   */
    float* out_cv = out + BATCH*HW;            /* [NCV]        */
    float* out_ch = out_cv + NCV;              /* [NCH]        */

    k_reset<<<1, 128>>>();
    k_coeff_v<<<(NCV + 255)/256, 256>>>(guide, out_cv);
    k_coeff_h<<<(NCH + 255)/256, 256>>>(guide, out_ch);

    dim3 grid(NBX, NBY, BATCH);
    k_persist<<<grid, NTHREADS>>>(initial, out_y);
}